// round 1
// baseline (speedup 1.0000x reference)
#include <cuda_runtime.h>
#include <math.h>

#define NMAX 8192
#define DMAX 128

// Scratch (no cudaMalloc allowed)
__device__ float g_pos_min[NMAX];
__device__ float g_pos_sum[NMAX];
__device__ float g_neg_sum[NMAX];
__device__ float g_last[4];   // [0]=pos_cnt [1]=pos_simsum [2]=neg_cnt [3]=neg_simsum

// -----------------------------------------------------------------------------
// Kernel 1: per-row positive pass (same-label pairs only) + zero accumulators.
// One warp per row. ep = EPOCH_NUM/300 = 1.0
// -----------------------------------------------------------------------------
__global__ void pos_pass(const float* __restrict__ x, const int* __restrict__ t,
                         int n, int d) {
    int gwarp = (blockIdx.x * blockDim.x + threadIdx.x) >> 5;
    int lane  = threadIdx.x & 31;
    if (gwarp >= n) return;
    int i = gwarp;

    __shared__ float4 sh[8 * (DMAX / 4)];
    int wlocal = threadIdx.x >> 5;
    float4* xi = sh + wlocal * (DMAX / 4);
    const float4* X = (const float4*)x;
    int d4 = d >> 2;
    for (int k = lane; k < d4; k += 32) xi[k] = X[(size_t)i * d4 + k];
    __syncwarp();

    int ti = t[i];
    float pmin = INFINITY, psum = 0.f, pcnt = 0.f, psim = 0.f;
    for (int j = lane; j < n; j += 32) {
        if (t[j] != ti) continue;
        const float4* xj = X + (size_t)j * d4;
        float s = 0.f;
        #pragma unroll 8
        for (int k = 0; k < d4; k++) {
            float4 a = xi[k], b = xj[k];
            s += a.x * b.x + a.y * b.y + a.z * b.z + a.w * b.w;
        }
        if (s < 0.9f) {   // pos_mask (diagonal excluded: sim_ii = 1.0)
            pmin = fminf(pmin, s);
            float dm = s - 0.9f;
            psum += expf(-2.f * (s - 0.5f) + dm * dm);
            pcnt += 1.f;
            psim += s;
        }
    }
    #pragma unroll
    for (int m = 16; m; m >>= 1) {
        pmin = fminf(pmin, __shfl_xor_sync(0xffffffffu, pmin, m));
        psum += __shfl_xor_sync(0xffffffffu, psum, m);
        pcnt += __shfl_xor_sync(0xffffffffu, pcnt, m);
        psim += __shfl_xor_sync(0xffffffffu, psim, m);
    }
    if (lane == 0) {
        g_pos_min[i] = pmin;
        g_pos_sum[i] = psum;
        g_neg_sum[i] = 0.f;
        if (i == n - 1) { g_last[0] = pcnt; g_last[1] = psim; }
        if (i == 0)     { g_last[2] = 0.f; g_last[3] = 0.f; }
    }
}

// -----------------------------------------------------------------------------
// Kernel 2: fused SGEMM (sim = x x^T) + negative-pair epilogue.
// BM=BN=128, BK=8, 256 threads, 8x8 micro-tile, double-buffered smem.
// -----------------------------------------------------------------------------
#define BM 128
#define BN 128
#define BK 8
#define TM 8
#define TN 8

__global__ __launch_bounds__(256, 2)
void neg_pass(const float* __restrict__ x, const int* __restrict__ t,
              int n, int d) {
    __shared__ float As[2][BK][BM];
    __shared__ float Bs[2][BK][BN];

    int tid = threadIdx.x;
    int tx = tid & 15, ty = tid >> 4;
    int i0 = blockIdx.y * BM, j0 = blockIdx.x * BN;

    int lrow = tid >> 1;           // 0..127
    int lseg = (tid & 1) * 4;      // 0 or 4 (float4 segment within BK=8)

    const float* Arow = x + (size_t)(i0 + lrow) * d + lseg;
    const float* Brow = x + (size_t)(j0 + lrow) * d + lseg;

    float acc[TM][TN];
    #pragma unroll
    for (int u = 0; u < TM; u++)
        #pragma unroll
        for (int v = 0; v < TN; v++) acc[u][v] = 0.f;

    // prologue
    float4 pa = *(const float4*)Arow;
    float4 pb = *(const float4*)Brow;
    As[0][lseg + 0][lrow] = pa.x; As[0][lseg + 1][lrow] = pa.y;
    As[0][lseg + 2][lrow] = pa.z; As[0][lseg + 3][lrow] = pa.w;
    Bs[0][lseg + 0][lrow] = pb.x; Bs[0][lseg + 1][lrow] = pb.y;
    Bs[0][lseg + 2][lrow] = pb.z; Bs[0][lseg + 3][lrow] = pb.w;
    __syncthreads();

    int ktiles = d / BK;
    int buf = 0;
    for (int kt = 0; kt < ktiles; kt++) {
        float4 na, nb;
        bool more = (kt + 1 < ktiles);
        if (more) {
            na = *(const float4*)(Arow + (kt + 1) * BK);
            nb = *(const float4*)(Brow + (kt + 1) * BK);
        }
        #pragma unroll
        for (int kk = 0; kk < BK; kk++) {
            float a[TM], b[TN];
            *(float4*)&a[0] = *(const float4*)&As[buf][kk][ty * TM + 0];
            *(float4*)&a[4] = *(const float4*)&As[buf][kk][ty * TM + 4];
            *(float4*)&b[0] = *(const float4*)&Bs[buf][kk][tx * TN + 0];
            *(float4*)&b[4] = *(const float4*)&Bs[buf][kk][tx * TN + 4];
            #pragma unroll
            for (int u = 0; u < TM; u++)
                #pragma unroll
                for (int v = 0; v < TN; v++) acc[u][v] += a[u] * b[v];
        }
        if (more) {
            int nb2 = buf ^ 1;
            As[nb2][lseg + 0][lrow] = na.x; As[nb2][lseg + 1][lrow] = na.y;
            As[nb2][lseg + 2][lrow] = na.z; As[nb2][lseg + 3][lrow] = na.w;
            Bs[nb2][lseg + 0][lrow] = nb.x; Bs[nb2][lseg + 1][lrow] = nb.y;
            Bs[nb2][lseg + 2][lrow] = nb.z; Bs[nb2][lseg + 3][lrow] = nb.w;
            __syncthreads();
            buf = nb2;
        }
    }

    // ---- epilogue: negative-pair terms ----
    int rowbase = i0 + ty * TM;
    int colbase = j0 + tx * TN;
    int tj[TN];
    #pragma unroll
    for (int v = 0; v < TN; v++) tj[v] = t[colbase + v];

    float nsum[TM];
    float lcnt = 0.f, lsim = 0.f;
    #pragma unroll
    for (int u = 0; u < TM; u++) {
        int row = rowbase + u;
        int ti = t[row];
        float pmin = g_pos_min[row];
        bool islast = (row == n - 1);
        float ns = 0.f;
        #pragma unroll
        for (int v = 0; v < TN; v++) {
            float s = acc[u][v];
            if (tj[v] != ti && s > 0.1f && s + 0.5f > pmin) {
                float dm = 0.1f - s;
                ns += expf(50.f * (s - 0.5f) + dm * dm);
                if (islast) { lcnt += 1.f; lsim += s; }
            }
        }
        nsum[u] = ns;
    }
    // reduce across the 16 tx threads (same-ty group == a 16-lane half-warp)
    #pragma unroll
    for (int u = 0; u < TM; u++) {
        float v = nsum[u];
        #pragma unroll
        for (int m = 1; m < 16; m <<= 1) v += __shfl_xor_sync(0xffffffffu, v, m);
        nsum[u] = v;
    }
    #pragma unroll
    for (int m = 1; m < 16; m <<= 1) {
        lcnt += __shfl_xor_sync(0xffffffffu, lcnt, m);
        lsim += __shfl_xor_sync(0xffffffffu, lsim, m);
    }
    if (tx == 0) {
        #pragma unroll
        for (int u = 0; u < TM; u++)
            atomicAdd(&g_neg_sum[rowbase + u], nsum[u]);
        if (rowbase <= n - 1 && n - 1 < rowbase + TM) {
            atomicAdd(&g_last[2], lcnt);
            atomicAdd(&g_last[3], lsim);
        }
    }
}

// -----------------------------------------------------------------------------
// Kernel 3: finalize — loss / prec / mean sims
// -----------------------------------------------------------------------------
__global__ void finalize(float* __restrict__ out, int n) {
    __shared__ float shl[8], shp[8];
    int tid = threadIdx.x;
    float loss = 0.f, noneg = 0.f;
    for (int i = tid; i < n; i += blockDim.x) {
        float ns = g_neg_sum[i];
        if (ns > 0.f) {
            loss += 0.5f * log1pf(g_pos_sum[i]) + (1.f / 50.f) * log1pf(ns);
        } else {
            noneg += 1.f;
        }
    }
    #pragma unroll
    for (int m = 16; m; m >>= 1) {
        loss  += __shfl_xor_sync(0xffffffffu, loss, m);
        noneg += __shfl_xor_sync(0xffffffffu, noneg, m);
    }
    int w = tid >> 5;
    if ((tid & 31) == 0) { shl[w] = loss; shp[w] = noneg; }
    __syncthreads();
    if (tid == 0) {
        float L = 0.f, P = 0.f;
        int nw = blockDim.x >> 5;
        for (int k = 0; k < nw; k++) { L += shl[k]; P += shp[k]; }
        out[0] = L / (float)n;
        out[1] = P / (float)n;
        out[2] = g_last[1] / fmaxf(g_last[0], 1.f);
        out[3] = g_last[3] / fmaxf(g_last[2], 1.f);
    }
}

// -----------------------------------------------------------------------------
extern "C" void kernel_launch(void* const* d_in, const int* in_sizes, int n_in,
                              void* d_out, int out_size) {
    const float* x = (const float*)d_in[0];
    const int*   t = (const int*)d_in[1];
    int n = in_sizes[1];
    int d = in_sizes[0] / n;
    float* out = (float*)d_out;

    // Kernel 1: 8 warps/block, 1 row per warp
    int blocks1 = (n + 7) / 8;
    pos_pass<<<blocks1, 256>>>(x, t, n, d);

    // Kernel 2: fused GEMM + neg epilogue
    dim3 grid2(n / BN, n / BM);
    neg_pass<<<grid2, 256>>>(x, t, n, d);

    // Kernel 3: finalize
    finalize<<<1, 256>>>(out, n);
}

// round 2
// speedup vs baseline: 2.1551x; 2.1551x over previous
#include <cuda_runtime.h>
#include <math.h>

#define NMAX 8192
#define DMAX 128
#define CAP  1024

// Scratch (no cudaMalloc allowed)
__device__ float g_pos_min[NMAX];
__device__ float g_pos_sum[NMAX];
__device__ float g_neg_sum[NMAX];
__device__ float g_last[4];   // [0]=pos_cnt [1]=pos_simsum [2]=neg_cnt [3]=neg_simsum

// -----------------------------------------------------------------------------
// Kernel 1: per-row positive pass. One warp per row.
// Phase A: ballot-compact same-label indices into a shared list.
// Phase B: dense dot products over the list, 4 independent accumulators.
// -----------------------------------------------------------------------------
__global__ __launch_bounds__(256)
void pos_pass(const float* __restrict__ x, const int* __restrict__ t,
              int n, int d) {
    __shared__ float4 shx[8 * (DMAX / 4)];     // 4 KB
    __shared__ int    lists[8][CAP];           // 32 KB

    int wl   = threadIdx.x >> 5;
    int lane = threadIdx.x & 31;
    int i = (blockIdx.x * blockDim.x + threadIdx.x) >> 5;
    if (i >= n) return;

    float4* xi = shx + wl * (DMAX / 4);
    const float4* X = (const float4*)x;
    int d4 = d >> 2;
    for (int k = lane; k < d4; k += 32) xi[k] = X[(size_t)i * d4 + k];

    int ti = t[i];
    int* list = lists[wl];

    // ---- compaction ----
    int cnt = 0;
    for (int j = lane; j < n; j += 32) {
        bool m = (t[j] == ti);
        unsigned bal = __ballot_sync(0xffffffffu, m);
        if (m) {
            int p = cnt + __popc(bal & ((1u << lane) - 1u));
            if (p < CAP) list[p] = j;
        }
        cnt += __popc(bal);
    }
    if (cnt > CAP) cnt = CAP;
    __syncwarp();

    // ---- dense dots over compacted list ----
    float pmin = INFINITY, psum = 0.f, pcnt = 0.f, psim = 0.f;
    for (int m = lane; m < cnt; m += 32) {
        int j = list[m];
        const float4* xj = X + (size_t)j * d4;
        float s0 = 0.f, s1 = 0.f, s2 = 0.f, s3 = 0.f;
        #pragma unroll 8
        for (int k = 0; k + 3 < d4; k += 4) {
            float4 a0 = xi[k + 0], b0 = xj[k + 0];
            float4 a1 = xi[k + 1], b1 = xj[k + 1];
            float4 a2 = xi[k + 2], b2 = xj[k + 2];
            float4 a3 = xi[k + 3], b3 = xj[k + 3];
            s0 += a0.x * b0.x + a0.y * b0.y + a0.z * b0.z + a0.w * b0.w;
            s1 += a1.x * b1.x + a1.y * b1.y + a1.z * b1.z + a1.w * b1.w;
            s2 += a2.x * b2.x + a2.y * b2.y + a2.z * b2.z + a2.w * b2.w;
            s3 += a3.x * b3.x + a3.y * b3.y + a3.z * b3.z + a3.w * b3.w;
        }
        float s = (s0 + s1) + (s2 + s3);
        if (s < 0.9f) {   // diagonal (s = 1.0) excluded numerically
            pmin = fminf(pmin, s);
            float dm = s - 0.9f;
            psum += expf(-2.f * (s - 0.5f) + dm * dm);
            pcnt += 1.f;
            psim += s;
        }
    }
    #pragma unroll
    for (int m = 16; m; m >>= 1) {
        pmin = fminf(pmin, __shfl_xor_sync(0xffffffffu, pmin, m));
        psum += __shfl_xor_sync(0xffffffffu, psum, m);
        pcnt += __shfl_xor_sync(0xffffffffu, pcnt, m);
        psim += __shfl_xor_sync(0xffffffffu, psim, m);
    }
    if (lane == 0) {
        g_pos_min[i] = pmin;
        g_pos_sum[i] = psum;
        g_neg_sum[i] = 0.f;
        if (i == n - 1) { g_last[0] = pcnt; g_last[1] = psim; }
        if (i == 0)     { g_last[2] = 0.f; g_last[3] = 0.f; }
    }
}

// -----------------------------------------------------------------------------
// Kernel 2: fused SGEMM (sim = x x^T) + symmetric negative-pair epilogue.
// Only blocks with j0 >= i0 compute; off-diagonal blocks credit BOTH the row
// direction (pair (i,j), gate pmin[i]) and the column direction (pair (j,i),
// gate pmin[j]) — exp term e(s) is shared.
// -----------------------------------------------------------------------------
#define BM 128
#define BN 128
#define BK 8
#define TM 8
#define TN 8

__global__ __launch_bounds__(256, 2)
void neg_pass(const float* __restrict__ x, const int* __restrict__ t,
              int n, int d) {
    int i0 = blockIdx.y * BM, j0 = blockIdx.x * BN;
    if (j0 < i0) return;                       // lower triangle: skip
    bool offdiag = (j0 > i0);

    __shared__ float As[2][BK][BM];
    __shared__ float Bs[2][BK][BN];
    __shared__ float srow[BM];
    __shared__ float scol[BN];
    __shared__ float slast2[2];

    int tid = threadIdx.x;
    int tx = tid & 15, ty = tid >> 4;

    int lrow = tid >> 1;           // 0..127
    int lseg = (tid & 1) * 4;      // 0 or 4

    const float* Arow = x + (size_t)(i0 + lrow) * d + lseg;
    const float* Brow = x + (size_t)(j0 + lrow) * d + lseg;

    float acc[TM][TN];
    #pragma unroll
    for (int u = 0; u < TM; u++)
        #pragma unroll
        for (int v = 0; v < TN; v++) acc[u][v] = 0.f;

    // zero epilogue accumulators early (before first sync)
    if (tid < BM) srow[tid] = 0.f;
    if (tid < BN) scol[tid] = 0.f;
    if (tid < 2)  slast2[tid] = 0.f;

    // prologue
    float4 pa = *(const float4*)Arow;
    float4 pb = *(const float4*)Brow;
    As[0][lseg + 0][lrow] = pa.x; As[0][lseg + 1][lrow] = pa.y;
    As[0][lseg + 2][lrow] = pa.z; As[0][lseg + 3][lrow] = pa.w;
    Bs[0][lseg + 0][lrow] = pb.x; Bs[0][lseg + 1][lrow] = pb.y;
    Bs[0][lseg + 2][lrow] = pb.z; Bs[0][lseg + 3][lrow] = pb.w;
    __syncthreads();

    int ktiles = d / BK;
    int buf = 0;
    for (int kt = 0; kt < ktiles; kt++) {
        float4 na, nb;
        bool more = (kt + 1 < ktiles);
        if (more) {
            na = *(const float4*)(Arow + (kt + 1) * BK);
            nb = *(const float4*)(Brow + (kt + 1) * BK);
        }
        #pragma unroll
        for (int kk = 0; kk < BK; kk++) {
            float a[TM], b[TN];
            *(float4*)&a[0] = *(const float4*)&As[buf][kk][ty * TM + 0];
            *(float4*)&a[4] = *(const float4*)&As[buf][kk][ty * TM + 4];
            *(float4*)&b[0] = *(const float4*)&Bs[buf][kk][tx * TN + 0];
            *(float4*)&b[4] = *(const float4*)&Bs[buf][kk][tx * TN + 4];
            #pragma unroll
            for (int u = 0; u < TM; u++)
                #pragma unroll
                for (int v = 0; v < TN; v++) acc[u][v] += a[u] * b[v];
        }
        if (more) {
            int nb2 = buf ^ 1;
            As[nb2][lseg + 0][lrow] = na.x; As[nb2][lseg + 1][lrow] = na.y;
            As[nb2][lseg + 2][lrow] = na.z; As[nb2][lseg + 3][lrow] = na.w;
            Bs[nb2][lseg + 0][lrow] = nb.x; Bs[nb2][lseg + 1][lrow] = nb.y;
            Bs[nb2][lseg + 2][lrow] = nb.z; Bs[nb2][lseg + 3][lrow] = nb.w;
            __syncthreads();
            buf = nb2;
        }
    }

    // ---- symmetric epilogue ----
    int rowbase = i0 + ty * TM;
    int colbase = j0 + tx * TN;

    int   ti_[TM]; float pminR[TM];
    int   tj_[TN]; float pminC[TN];
    #pragma unroll
    for (int u = 0; u < TM; u++) {
        ti_[u]  = t[rowbase + u];
        pminR[u] = g_pos_min[rowbase + u];
    }
    #pragma unroll
    for (int v = 0; v < TN; v++) {
        tj_[v]  = t[colbase + v];
        pminC[v] = g_pos_min[colbase + v];
    }

    float rsum[TM], csum[TN];
    #pragma unroll
    for (int u = 0; u < TM; u++) rsum[u] = 0.f;
    #pragma unroll
    for (int v = 0; v < TN; v++) csum[v] = 0.f;
    float lcnt = 0.f, lsim = 0.f;

    #pragma unroll
    for (int u = 0; u < TM; u++) {
        bool rowlast = (rowbase + u == n - 1);
        #pragma unroll
        for (int v = 0; v < TN; v++) {
            float s = acc[u][v];
            if (tj_[v] != ti_[u] && s > 0.1f) {
                float dm = 0.1f - s;
                float e = expf(50.f * (s - 0.5f) + dm * dm);
                if (s + 0.5f > pminR[u]) {
                    rsum[u] += e;
                    if (rowlast) { lcnt += 1.f; lsim += s; }
                }
                if (offdiag && s + 0.5f > pminC[v]) {
                    csum[v] += e;
                    if (colbase + v == n - 1) { lcnt += 1.f; lsim += s; }
                }
            }
        }
    }

    __syncthreads();   // ensure GEMM smem reads done & srow/scol zeroed visible
    #pragma unroll
    for (int u = 0; u < TM; u++)
        if (rsum[u] != 0.f) atomicAdd(&srow[ty * TM + u], rsum[u]);
    if (offdiag) {
        #pragma unroll
        for (int v = 0; v < TN; v++)
            if (csum[v] != 0.f) atomicAdd(&scol[tx * TN + v], csum[v]);
    }
    if (lcnt != 0.f) {
        atomicAdd(&slast2[0], lcnt);
        atomicAdd(&slast2[1], lsim);
    }
    __syncthreads();

    if (tid < BM && srow[tid] != 0.f) atomicAdd(&g_neg_sum[i0 + tid], srow[tid]);
    if (offdiag && tid < BN && scol[tid] != 0.f) atomicAdd(&g_neg_sum[j0 + tid], scol[tid]);
    if (tid == 0 && slast2[0] != 0.f) {
        atomicAdd(&g_last[2], slast2[0]);
        atomicAdd(&g_last[3], slast2[1]);
    }
}

// -----------------------------------------------------------------------------
// Kernel 3: finalize — loss / prec / mean sims
// -----------------------------------------------------------------------------
__global__ void finalize(float* __restrict__ out, int n) {
    __shared__ float shl[8], shp[8];
    int tid = threadIdx.x;
    float loss = 0.f, noneg = 0.f;
    for (int i = tid; i < n; i += blockDim.x) {
        float ns = g_neg_sum[i];
        if (ns > 0.f) {
            loss += 0.5f * log1pf(g_pos_sum[i]) + (1.f / 50.f) * log1pf(ns);
        } else {
            noneg += 1.f;
        }
    }
    #pragma unroll
    for (int m = 16; m; m >>= 1) {
        loss  += __shfl_xor_sync(0xffffffffu, loss, m);
        noneg += __shfl_xor_sync(0xffffffffu, noneg, m);
    }
    int w = tid >> 5;
    if ((tid & 31) == 0) { shl[w] = loss; shp[w] = noneg; }
    __syncthreads();
    if (tid == 0) {
        float L = 0.f, P = 0.f;
        int nw = blockDim.x >> 5;
        for (int k = 0; k < nw; k++) { L += shl[k]; P += shp[k]; }
        out[0] = L / (float)n;
        out[1] = P / (float)n;
        out[2] = g_last[1] / fmaxf(g_last[0], 1.f);
        out[3] = g_last[3] / fmaxf(g_last[2], 1.f);
    }
}

// -----------------------------------------------------------------------------
extern "C" void kernel_launch(void* const* d_in, const int* in_sizes, int n_in,
                              void* d_out, int out_size) {
    const float* x = (const float*)d_in[0];
    const int*   t = (const int*)d_in[1];
    int n = in_sizes[1];
    int d = in_sizes[0] / n;
    float* out = (float*)d_out;

    int blocks1 = (n + 7) / 8;
    pos_pass<<<blocks1, 256>>>(x, t, n, d);

    dim3 grid2(n / BN, n / BM);
    neg_pass<<<grid2, 256>>>(x, t, n, d);

    finalize<<<1, 256>>>(out, n);
}

// round 3
// speedup vs baseline: 2.4997x; 1.1599x over previous
#include <cuda_runtime.h>
#include <math.h>

#define NMAX 8192
#define DMAX 128
#define NCLS 128          // labels are in [0,100); pad to 128

// Scratch (no cudaMalloc allowed)
__device__ float g_pos_min[NMAX];
__device__ float g_pos_sum[NMAX];
__device__ float g_neg_sum[NMAX];
__device__ float g_last[4];       // [0]=pos_cnt [1]=pos_simsum [2]=neg_cnt [3]=neg_simsum
__device__ int   g_cls_cnt[NCLS];
__device__ int   g_cls_off[NCLS + 1];
__device__ int   g_cls_cur[NCLS];
__device__ int   g_cls_list[NMAX];

// -----------------------------------------------------------------------------
// Setup kernels: class histogram -> offsets -> scatter
// -----------------------------------------------------------------------------
__global__ void k_zero() {
    int i = threadIdx.x;
    if (i < NCLS) { g_cls_cnt[i] = 0; g_cls_cur[i] = 0; }
    if (i < 4) g_last[i] = 0.f;
}

__global__ void k_hist(const int* __restrict__ t, int n) {
    int i = blockIdx.x * blockDim.x + threadIdx.x;
    if (i < n) atomicAdd(&g_cls_cnt[t[i]], 1);
}

__global__ void k_scan() {
    // single thread: 128 elements, trivial
    if (threadIdx.x == 0) {
        int acc = 0;
        for (int c = 0; c < NCLS; c++) { g_cls_off[c] = acc; acc += g_cls_cnt[c]; }
        g_cls_off[NCLS] = acc;
    }
}

__global__ void k_scatter(const int* __restrict__ t, int n) {
    int i = blockIdx.x * blockDim.x + threadIdx.x;
    if (i < n) {
        int c = t[i];
        int p = atomicAdd(&g_cls_cur[c], 1);
        g_cls_list[g_cls_off[c] + p] = i;
    }
}

// -----------------------------------------------------------------------------
// Kernel 1: per-row positive pass over precomputed class list. Warp per row.
// -----------------------------------------------------------------------------
__global__ __launch_bounds__(256)
void pos_pass(const float* __restrict__ x, const int* __restrict__ t, int n, int d) {
    __shared__ float4 shx[8 * (DMAX / 4)];

    int wl   = threadIdx.x >> 5;
    int lane = threadIdx.x & 31;
    int i = (blockIdx.x * blockDim.x + threadIdx.x) >> 5;
    if (i >= n) return;

    float4* xi = shx + wl * (DMAX / 4);
    const float4* X = (const float4*)x;
    int d4 = d >> 2;
    for (int k = lane; k < d4; k += 32) xi[k] = X[(size_t)i * d4 + k];
    __syncwarp();

    int c   = t[i];
    int beg = g_cls_off[c];
    int end = g_cls_off[c + 1];

    float pmin = INFINITY, psum = 0.f, pcnt = 0.f, psim = 0.f;
    for (int m = beg + lane; m < end; m += 32) {
        int j = g_cls_list[m];
        const float4* xj = X + (size_t)j * d4;
        float s0 = 0.f, s1 = 0.f, s2 = 0.f, s3 = 0.f;
        #pragma unroll 8
        for (int k = 0; k + 3 < d4; k += 4) {
            float4 a0 = xi[k + 0], b0 = xj[k + 0];
            float4 a1 = xi[k + 1], b1 = xj[k + 1];
            float4 a2 = xi[k + 2], b2 = xj[k + 2];
            float4 a3 = xi[k + 3], b3 = xj[k + 3];
            s0 += a0.x * b0.x + a0.y * b0.y + a0.z * b0.z + a0.w * b0.w;
            s1 += a1.x * b1.x + a1.y * b1.y + a1.z * b1.z + a1.w * b1.w;
            s2 += a2.x * b2.x + a2.y * b2.y + a2.z * b2.z + a2.w * b2.w;
            s3 += a3.x * b3.x + a3.y * b3.y + a3.z * b3.z + a3.w * b3.w;
        }
        float s = (s0 + s1) + (s2 + s3);
        if (s < 0.9f) {   // diagonal (s = 1.0) excluded numerically
            pmin = fminf(pmin, s);
            float dm = s - 0.9f;
            psum += expf(-2.f * (s - 0.5f) + dm * dm);
            pcnt += 1.f;
            psim += s;
        }
    }
    #pragma unroll
    for (int m = 16; m; m >>= 1) {
        pmin = fminf(pmin, __shfl_xor_sync(0xffffffffu, pmin, m));
        psum += __shfl_xor_sync(0xffffffffu, psum, m);
        pcnt += __shfl_xor_sync(0xffffffffu, pcnt, m);
        psim += __shfl_xor_sync(0xffffffffu, psim, m);
    }
    if (lane == 0) {
        g_pos_min[i] = pmin;
        g_pos_sum[i] = psum;
        g_neg_sum[i] = 0.f;
        if (i == n - 1) { g_last[0] = pcnt; g_last[1] = psim; }
    }
}

// -----------------------------------------------------------------------------
// Kernel 2: fused SGEMM (sim = x x^T) + symmetric negative-pair epilogue.
// Only j0 >= i0 blocks compute; off-diagonal blocks credit BOTH directions.
// -----------------------------------------------------------------------------
#define BM 128
#define BN 128
#define BK 8
#define TM 8
#define TN 8

__global__ __launch_bounds__(256, 2)
void neg_pass(const float* __restrict__ x, const int* __restrict__ t,
              int n, int d) {
    int i0 = blockIdx.y * BM, j0 = blockIdx.x * BN;
    if (j0 < i0) return;
    bool offdiag = (j0 > i0);

    __shared__ float As[2][BK][BM];
    __shared__ float Bs[2][BK][BN];
    __shared__ float srow[BM];
    __shared__ float scol[BN];
    __shared__ float slast2[2];

    int tid = threadIdx.x;
    int tx = tid & 15, ty = tid >> 4;

    int lrow = tid >> 1;
    int lseg = (tid & 1) * 4;

    const float* Arow = x + (size_t)(i0 + lrow) * d + lseg;
    const float* Brow = x + (size_t)(j0 + lrow) * d + lseg;

    float acc[TM][TN];
    #pragma unroll
    for (int u = 0; u < TM; u++)
        #pragma unroll
        for (int v = 0; v < TN; v++) acc[u][v] = 0.f;

    if (tid < BM) srow[tid] = 0.f;
    if (tid < BN) scol[tid] = 0.f;
    if (tid < 2)  slast2[tid] = 0.f;

    float4 pa = *(const float4*)Arow;
    float4 pb = *(const float4*)Brow;
    As[0][lseg + 0][lrow] = pa.x; As[0][lseg + 1][lrow] = pa.y;
    As[0][lseg + 2][lrow] = pa.z; As[0][lseg + 3][lrow] = pa.w;
    Bs[0][lseg + 0][lrow] = pb.x; Bs[0][lseg + 1][lrow] = pb.y;
    Bs[0][lseg + 2][lrow] = pb.z; Bs[0][lseg + 3][lrow] = pb.w;
    __syncthreads();

    int ktiles = d / BK;
    int buf = 0;
    for (int kt = 0; kt < ktiles; kt++) {
        float4 na, nb;
        bool more = (kt + 1 < ktiles);
        if (more) {
            na = *(const float4*)(Arow + (kt + 1) * BK);
            nb = *(const float4*)(Brow + (kt + 1) * BK);
        }
        #pragma unroll
        for (int kk = 0; kk < BK; kk++) {
            float a[TM], b[TN];
            *(float4*)&a[0] = *(const float4*)&As[buf][kk][ty * TM + 0];
            *(float4*)&a[4] = *(const float4*)&As[buf][kk][ty * TM + 4];
            *(float4*)&b[0] = *(const float4*)&Bs[buf][kk][tx * TN + 0];
            *(float4*)&b[4] = *(const float4*)&Bs[buf][kk][tx * TN + 4];
            #pragma unroll
            for (int u = 0; u < TM; u++)
                #pragma unroll
                for (int v = 0; v < TN; v++) acc[u][v] += a[u] * b[v];
        }
        if (more) {
            int nb2 = buf ^ 1;
            As[nb2][lseg + 0][lrow] = na.x; As[nb2][lseg + 1][lrow] = na.y;
            As[nb2][lseg + 2][lrow] = na.z; As[nb2][lseg + 3][lrow] = na.w;
            Bs[nb2][lseg + 0][lrow] = nb.x; Bs[nb2][lseg + 1][lrow] = nb.y;
            Bs[nb2][lseg + 2][lrow] = nb.z; Bs[nb2][lseg + 3][lrow] = nb.w;
            __syncthreads();
            buf = nb2;
        }
    }

    int rowbase = i0 + ty * TM;
    int colbase = j0 + tx * TN;

    int   ti_[TM]; float pminR[TM];
    int   tj_[TN]; float pminC[TN];
    #pragma unroll
    for (int u = 0; u < TM; u++) {
        ti_[u]   = t[rowbase + u];
        pminR[u] = g_pos_min[rowbase + u];
    }
    #pragma unroll
    for (int v = 0; v < TN; v++) {
        tj_[v]   = t[colbase + v];
        pminC[v] = g_pos_min[colbase + v];
    }

    float rsum[TM], csum[TN];
    #pragma unroll
    for (int u = 0; u < TM; u++) rsum[u] = 0.f;
    #pragma unroll
    for (int v = 0; v < TN; v++) csum[v] = 0.f;
    float lcnt = 0.f, lsim = 0.f;

    #pragma unroll
    for (int u = 0; u < TM; u++) {
        bool rowlast = (rowbase + u == n - 1);
        #pragma unroll
        for (int v = 0; v < TN; v++) {
            float s = acc[u][v];
            if (tj_[v] != ti_[u] && s > 0.1f) {
                float dm = 0.1f - s;
                float e = expf(50.f * (s - 0.5f) + dm * dm);
                if (s + 0.5f > pminR[u]) {
                    rsum[u] += e;
                    if (rowlast) { lcnt += 1.f; lsim += s; }
                }
                if (offdiag && s + 0.5f > pminC[v]) {
                    csum[v] += e;
                    if (colbase + v == n - 1) { lcnt += 1.f; lsim += s; }
                }
            }
        }
    }

    __syncthreads();
    #pragma unroll
    for (int u = 0; u < TM; u++)
        if (rsum[u] != 0.f) atomicAdd(&srow[ty * TM + u], rsum[u]);
    if (offdiag) {
        #pragma unroll
        for (int v = 0; v < TN; v++)
            if (csum[v] != 0.f) atomicAdd(&scol[tx * TN + v], csum[v]);
    }
    if (lcnt != 0.f) {
        atomicAdd(&slast2[0], lcnt);
        atomicAdd(&slast2[1], lsim);
    }
    __syncthreads();

    if (tid < BM && srow[tid] != 0.f) atomicAdd(&g_neg_sum[i0 + tid], srow[tid]);
    if (offdiag && tid < BN && scol[tid] != 0.f) atomicAdd(&g_neg_sum[j0 + tid], scol[tid]);
    if (tid == 0 && slast2[0] != 0.f) {
        atomicAdd(&g_last[2], slast2[0]);
        atomicAdd(&g_last[3], slast2[1]);
    }
}

// -----------------------------------------------------------------------------
// Kernel 3: finalize
// -----------------------------------------------------------------------------
__global__ void finalize(float* __restrict__ out, int n) {
    __shared__ float shl[8], shp[8];
    int tid = threadIdx.x;
    float loss = 0.f, noneg = 0.f;
    for (int i = tid; i < n; i += blockDim.x) {
        float ns = g_neg_sum[i];
        if (ns > 0.f) {
            loss += 0.5f * log1pf(g_pos_sum[i]) + (1.f / 50.f) * log1pf(ns);
        } else {
            noneg += 1.f;
        }
    }
    #pragma unroll
    for (int m = 16; m; m >>= 1) {
        loss  += __shfl_xor_sync(0xffffffffu, loss, m);
        noneg += __shfl_xor_sync(0xffffffffu, noneg, m);
    }
    int w = tid >> 5;
    if ((tid & 31) == 0) { shl[w] = loss; shp[w] = noneg; }
    __syncthreads();
    if (tid == 0) {
        float L = 0.f, P = 0.f;
        int nw = blockDim.x >> 5;
        for (int k = 0; k < nw; k++) { L += shl[k]; P += shp[k]; }
        out[0] = L / (float)n;
        out[1] = P / (float)n;
        out[2] = g_last[1] / fmaxf(g_last[0], 1.f);
        out[3] = g_last[3] / fmaxf(g_last[2], 1.f);
    }
}

// -----------------------------------------------------------------------------
extern "C" void kernel_launch(void* const* d_in, const int* in_sizes, int n_in,
                              void* d_out, int out_size) {
    const float* x = (const float*)d_in[0];
    const int*   t = (const int*)d_in[1];
    int n = in_sizes[1];
    int d = in_sizes[0] / n;
    float* out = (float*)d_out;

    k_zero<<<1, 128>>>();
    k_hist<<<(n + 255) / 256, 256>>>(t, n);
    k_scan<<<1, 32>>>();
    k_scatter<<<(n + 255) / 256, 256>>>(t, n);

    pos_pass<<<(n + 7) / 8, 256>>>(x, t, n, d);

    dim3 grid2(n / BN, n / BM);
    neg_pass<<<grid2, 256>>>(x, t, n, d);

    finalize<<<1, 256>>>(out, n);
}

// round 4
// speedup vs baseline: 2.5865x; 1.0347x over previous
#include <cuda_runtime.h>
#include <cuda_bf16.h>
#include <math.h>

#define NMAX 8192
#define DMAX 128
#define NCLS 128

// Scratch (no cudaMalloc allowed)
__device__ float g_pos_min[NMAX];
__device__ float g_pos_sum[NMAX];
__device__ float g_neg_sum[NMAX];
__device__ float g_last[4];       // [0]=pos_cnt [1]=pos_simsum [2]=neg_cnt [3]=neg_simsum
__device__ int   g_cls_cnt[NCLS];
__device__ int   g_cls_off[NCLS + 1];
__device__ int   g_cls_cur[NCLS];
__device__ int   g_cls_list[NMAX];
__device__ __nv_bfloat16 g_xhi[NMAX * DMAX];
__device__ __nv_bfloat16 g_xlo[NMAX * DMAX];

// -----------------------------------------------------------------------------
// Setup: class histogram -> offsets -> scatter ; bf16 split
// -----------------------------------------------------------------------------
__global__ void k_zero() {
    int i = threadIdx.x;
    if (i < NCLS) { g_cls_cnt[i] = 0; g_cls_cur[i] = 0; }
    if (i < 4) g_last[i] = 0.f;
}

__global__ void k_hist(const int* __restrict__ t, int n) {
    int i = blockIdx.x * blockDim.x + threadIdx.x;
    if (i < n) atomicAdd(&g_cls_cnt[t[i]], 1);
}

__global__ void k_scan() {
    if (threadIdx.x == 0) {
        int acc = 0;
        for (int c = 0; c < NCLS; c++) { g_cls_off[c] = acc; acc += g_cls_cnt[c]; }
        g_cls_off[NCLS] = acc;
    }
}

__global__ void k_scatter(const int* __restrict__ t, int n) {
    int i = blockIdx.x * blockDim.x + threadIdx.x;
    if (i < n) {
        int c = t[i];
        int p = atomicAdd(&g_cls_cur[c], 1);
        g_cls_list[g_cls_off[c] + p] = i;
    }
}

__global__ void k_split(const float* __restrict__ x, int total) {
    int i = blockIdx.x * blockDim.x + threadIdx.x;
    if (i < total) {
        float v = x[i];
        __nv_bfloat16 hi = __float2bfloat16(v);
        float lo = v - __bfloat162float(hi);
        g_xhi[i] = hi;
        g_xlo[i] = __float2bfloat16(lo);
    }
}

// -----------------------------------------------------------------------------
// Kernel 1: positive pass over precomputed class list (exact fp32). Warp/row.
// -----------------------------------------------------------------------------
__global__ __launch_bounds__(256)
void pos_pass(const float* __restrict__ x, const int* __restrict__ t, int n, int d) {
    __shared__ float4 shx[8 * (DMAX / 4)];

    int wl   = threadIdx.x >> 5;
    int lane = threadIdx.x & 31;
    int i = (blockIdx.x * blockDim.x + threadIdx.x) >> 5;
    if (i >= n) return;

    float4* xi = shx + wl * (DMAX / 4);
    const float4* X = (const float4*)x;
    int d4 = d >> 2;
    for (int k = lane; k < d4; k += 32) xi[k] = X[(size_t)i * d4 + k];
    __syncwarp();

    int c   = t[i];
    int beg = g_cls_off[c];
    int end = g_cls_off[c + 1];

    float pmin = INFINITY, psum = 0.f, pcnt = 0.f, psim = 0.f;
    for (int m = beg + lane; m < end; m += 32) {
        int j = g_cls_list[m];
        const float4* xj = X + (size_t)j * d4;
        float s0 = 0.f, s1 = 0.f, s2 = 0.f, s3 = 0.f;
        #pragma unroll 8
        for (int k = 0; k + 3 < d4; k += 4) {
            float4 a0 = xi[k + 0], b0 = xj[k + 0];
            float4 a1 = xi[k + 1], b1 = xj[k + 1];
            float4 a2 = xi[k + 2], b2 = xj[k + 2];
            float4 a3 = xi[k + 3], b3 = xj[k + 3];
            s0 += a0.x * b0.x + a0.y * b0.y + a0.z * b0.z + a0.w * b0.w;
            s1 += a1.x * b1.x + a1.y * b1.y + a1.z * b1.z + a1.w * b1.w;
            s2 += a2.x * b2.x + a2.y * b2.y + a2.z * b2.z + a2.w * b2.w;
            s3 += a3.x * b3.x + a3.y * b3.y + a3.z * b3.z + a3.w * b3.w;
        }
        float s = (s0 + s1) + (s2 + s3);
        if (s < 0.9f) {
            pmin = fminf(pmin, s);
            float dm = s - 0.9f;
            psum += expf(-2.f * (s - 0.5f) + dm * dm);
            pcnt += 1.f;
            psim += s;
        }
    }
    #pragma unroll
    for (int m = 16; m; m >>= 1) {
        pmin = fminf(pmin, __shfl_xor_sync(0xffffffffu, pmin, m));
        psum += __shfl_xor_sync(0xffffffffu, psum, m);
        pcnt += __shfl_xor_sync(0xffffffffu, pcnt, m);
        psim += __shfl_xor_sync(0xffffffffu, psim, m);
    }
    if (lane == 0) {
        g_pos_min[i] = pmin;
        g_pos_sum[i] = psum;
        g_neg_sum[i] = 0.f;
        if (i == n - 1) { g_last[0] = pcnt; g_last[1] = psim; }
    }
}

// -----------------------------------------------------------------------------
// Kernel 2: tensor-core (bf16-split) GEMM + symmetric negative epilogue.
// 128x128 tile/CTA, 256 thr = 8 warps (2x4), warp tile 64x32 via mma.m16n8k16.
// sim = hi*hi + hi*lo + lo*hi  (fp32 accum).
// -----------------------------------------------------------------------------
#define BT   128
#define PAD  136          // bf16 elements per padded smem row (conflict-free)
#define TILE_ELN (BT * PAD)

__device__ __forceinline__ void mma16816(float* c, const unsigned* a, const unsigned* b) {
    asm volatile(
        "mma.sync.aligned.m16n8k16.row.col.f32.bf16.bf16.f32 "
        "{%0,%1,%2,%3}, {%4,%5,%6,%7}, {%8,%9}, {%0,%1,%2,%3};"
        : "+f"(c[0]), "+f"(c[1]), "+f"(c[2]), "+f"(c[3])
        : "r"(a[0]), "r"(a[1]), "r"(a[2]), "r"(a[3]), "r"(b[0]), "r"(b[1]));
}

__global__ __launch_bounds__(256, 1)
void neg_pass_tc(const int* __restrict__ t, int n, int d) {
    int i0 = blockIdx.y * BT, j0 = blockIdx.x * BT;
    if (j0 < i0) return;
    bool offdiag = (j0 > i0);

    extern __shared__ __nv_bfloat16 smem[];
    __nv_bfloat16* Ahi = smem;
    __nv_bfloat16* Alo = smem + TILE_ELN;
    __nv_bfloat16* Bhi = smem + 2 * TILE_ELN;
    __nv_bfloat16* Blo = smem + 3 * TILE_ELN;

    __shared__ float srow[BT];
    __shared__ float scol[BT];
    __shared__ float slast2[2];

    int tid  = threadIdx.x;
    int lane = tid & 31;
    int w    = tid >> 5;
    int wm   = w >> 2;       // 0..1  -> rows wm*64
    int wn   = w & 3;        // 0..3  -> cols wn*32

    if (tid < BT) { srow[tid] = 0.f; scol[tid] = 0.f; }
    if (tid < 2)  slast2[tid] = 0.f;

    // ---- load 4 tiles into padded smem (uint4 = 8 bf16) ----
    {
        int row  = tid >> 1;          // 0..127
        int half = tid & 1;           // 0,1
        int qph  = d / 16;            // uint4 per half-row (8 for d=128)
        const uint4* srcAh = (const uint4*)(g_xhi + (size_t)(i0 + row) * d) + half * qph;
        const uint4* srcAl = (const uint4*)(g_xlo + (size_t)(i0 + row) * d) + half * qph;
        const uint4* srcBh = (const uint4*)(g_xhi + (size_t)(j0 + row) * d) + half * qph;
        const uint4* srcBl = (const uint4*)(g_xlo + (size_t)(j0 + row) * d) + half * qph;
        uint4* dAh = (uint4*)(Ahi + row * PAD + half * (d / 2));
        uint4* dAl = (uint4*)(Alo + row * PAD + half * (d / 2));
        uint4* dBh = (uint4*)(Bhi + row * PAD + half * (d / 2));
        uint4* dBl = (uint4*)(Blo + row * PAD + half * (d / 2));
        #pragma unroll
        for (int q = 0; q < 8; q++) {
            if (q < qph) {
                dAh[q] = srcAh[q];
                dAl[q] = srcAl[q];
                dBh[q] = srcBh[q];
                dBl[q] = srcBl[q];
            }
        }
    }
    __syncthreads();

    // ---- MMA compute ----
    float acc[4][4][4];
    #pragma unroll
    for (int mf = 0; mf < 4; mf++)
        #pragma unroll
        for (int nf = 0; nf < 4; nf++)
            #pragma unroll
            for (int r = 0; r < 4; r++) acc[mf][nf][r] = 0.f;

    int q  = lane >> 2;      // 0..7
    int tq = lane & 3;       // 0..3
    int nkc = d / 16;

    #pragma unroll
    for (int p = 0; p < 3; p++) {
        const __nv_bfloat16* As = (p == 2) ? Alo : Ahi;
        const __nv_bfloat16* Bs = (p == 1) ? Blo : Bhi;
        for (int kc = 0; kc < nkc; kc++) {
            int k0 = kc * 16;
            unsigned a[4][4], b[4][2];
            #pragma unroll
            for (int mf = 0; mf < 4; mf++) {
                int r0 = wm * 64 + mf * 16 + q;
                const __nv_bfloat16* base = As + r0 * PAD + k0 + tq * 2;
                a[mf][0] = *(const unsigned*)(base);
                a[mf][1] = *(const unsigned*)(base + 8 * PAD);
                a[mf][2] = *(const unsigned*)(base + 8);
                a[mf][3] = *(const unsigned*)(base + 8 * PAD + 8);
            }
            #pragma unroll
            for (int nf = 0; nf < 4; nf++) {
                int c0 = wn * 32 + nf * 8 + q;
                const __nv_bfloat16* base = Bs + c0 * PAD + k0 + tq * 2;
                b[nf][0] = *(const unsigned*)(base);
                b[nf][1] = *(const unsigned*)(base + 8);
            }
            #pragma unroll
            for (int mf = 0; mf < 4; mf++)
                #pragma unroll
                for (int nf = 0; nf < 4; nf++)
                    mma16816(acc[mf][nf], a[mf], b[nf]);
        }
    }

    // ---- epilogue ----
    // element (mf,nf,r): row = i0+wm*64+mf*16+q+8*(r>>1), col = j0+wn*32+nf*8+tq*2+(r&1)
    int   tti[8]; float tpmR[8];   // index ri = mf*2 + (r>>1)
    int   ttj[8]; float tpmC[8];   // index ci = nf*2 + (r&1)
    #pragma unroll
    for (int mf = 0; mf < 4; mf++)
        #pragma unroll
        for (int rh = 0; rh < 2; rh++) {
            int row = i0 + wm * 64 + mf * 16 + q + rh * 8;
            tti[mf * 2 + rh]  = t[row];
            tpmR[mf * 2 + rh] = g_pos_min[row];
        }
    #pragma unroll
    for (int nf = 0; nf < 4; nf++)
        #pragma unroll
        for (int cl = 0; cl < 2; cl++) {
            int col = j0 + wn * 32 + nf * 8 + tq * 2 + cl;
            ttj[nf * 2 + cl]  = t[col];
            tpmC[nf * 2 + cl] = g_pos_min[col];
        }

    float rsum[8], csum[8];
    #pragma unroll
    for (int k = 0; k < 8; k++) { rsum[k] = 0.f; csum[k] = 0.f; }

    #pragma unroll
    for (int mf = 0; mf < 4; mf++) {
        #pragma unroll
        for (int nf = 0; nf < 4; nf++) {
            #pragma unroll
            for (int r = 0; r < 4; r++) {
                float s = acc[mf][nf][r];
                int ri = mf * 2 + (r >> 1);
                int ci = nf * 2 + (r & 1);
                if (ttj[ci] != tti[ri] && s > 0.1f) {
                    float dm = 0.1f - s;
                    float e = expf(50.f * (s - 0.5f) + dm * dm);
                    bool gr = (s + 0.5f > tpmR[ri]);
                    bool gc = offdiag && (s + 0.5f > tpmC[ci]);
                    if (gr) {
                        rsum[ri] += e;
                        int row = i0 + wm * 64 + mf * 16 + q + (r >> 1) * 8;
                        if (row == n - 1) {
                            atomicAdd(&slast2[0], 1.f);
                            atomicAdd(&slast2[1], s);
                        }
                    }
                    if (gc) {
                        csum[ci] += e;
                        int col = j0 + wn * 32 + nf * 8 + tq * 2 + (r & 1);
                        if (col == n - 1) {
                            atomicAdd(&slast2[0], 1.f);
                            atomicAdd(&slast2[1], s);
                        }
                    }
                }
            }
        }
    }

    // row sums: reduce over tq (lanes xor 1,2)
    #pragma unroll
    for (int ri = 0; ri < 8; ri++) {
        float v = rsum[ri];
        v += __shfl_xor_sync(0xffffffffu, v, 1);
        v += __shfl_xor_sync(0xffffffffu, v, 2);
        if (tq == 0 && v != 0.f) {
            int mf = ri >> 1, rh = ri & 1;
            atomicAdd(&srow[wm * 64 + mf * 16 + q + rh * 8], v);
        }
    }
    // col sums: reduce over q (lanes xor 4,8,16)
    if (offdiag) {
        #pragma unroll
        for (int ci = 0; ci < 8; ci++) {
            float v = csum[ci];
            v += __shfl_xor_sync(0xffffffffu, v, 4);
            v += __shfl_xor_sync(0xffffffffu, v, 8);
            v += __shfl_xor_sync(0xffffffffu, v, 16);
            if (q == 0 && v != 0.f) {
                int nf = ci >> 1, cl = ci & 1;
                atomicAdd(&scol[wn * 32 + nf * 8 + tq * 2 + cl], v);
            }
        }
    }
    __syncthreads();

    if (tid < BT && srow[tid] != 0.f) atomicAdd(&g_neg_sum[i0 + tid], srow[tid]);
    if (offdiag && tid < BT && scol[tid] != 0.f) atomicAdd(&g_neg_sum[j0 + tid], scol[tid]);
    if (tid == 0 && slast2[0] != 0.f) {
        atomicAdd(&g_last[2], slast2[0]);
        atomicAdd(&g_last[3], slast2[1]);
    }
}

// -----------------------------------------------------------------------------
// Kernel 3: finalize
// -----------------------------------------------------------------------------
__global__ void finalize(float* __restrict__ out, int n) {
    __shared__ float shl[8], shp[8];
    int tid = threadIdx.x;
    float loss = 0.f, noneg = 0.f;
    for (int i = tid; i < n; i += blockDim.x) {
        float ns = g_neg_sum[i];
        if (ns > 0.f) {
            loss += 0.5f * log1pf(g_pos_sum[i]) + (1.f / 50.f) * log1pf(ns);
        } else {
            noneg += 1.f;
        }
    }
    #pragma unroll
    for (int m = 16; m; m >>= 1) {
        loss  += __shfl_xor_sync(0xffffffffu, loss, m);
        noneg += __shfl_xor_sync(0xffffffffu, noneg, m);
    }
    int w = tid >> 5;
    if ((tid & 31) == 0) { shl[w] = loss; shp[w] = noneg; }
    __syncthreads();
    if (tid == 0) {
        float L = 0.f, P = 0.f;
        int nw = blockDim.x >> 5;
        for (int k = 0; k < nw; k++) { L += shl[k]; P += shp[k]; }
        out[0] = L / (float)n;
        out[1] = P / (float)n;
        out[2] = g_last[1] / fmaxf(g_last[0], 1.f);
        out[3] = g_last[3] / fmaxf(g_last[2], 1.f);
    }
}

// -----------------------------------------------------------------------------
extern "C" void kernel_launch(void* const* d_in, const int* in_sizes, int n_in,
                              void* d_out, int out_size) {
    const float* x = (const float*)d_in[0];
    const int*   t = (const int*)d_in[1];
    int n = in_sizes[1];
    int d = in_sizes[0] / n;
    float* out = (float*)d_out;

    static bool attr_done = false;
    if (!attr_done) {
        cudaFuncSetAttribute(neg_pass_tc, cudaFuncAttributeMaxDynamicSharedMemorySize,
                             4 * TILE_ELN * (int)sizeof(__nv_bfloat16));
        attr_done = true;
    }

    k_zero<<<1, 128>>>();
    k_hist<<<(n + 255) / 256, 256>>>(t, n);
    k_scan<<<1, 32>>>();
    k_scatter<<<(n + 255) / 256, 256>>>(t, n);
    k_split<<<(n * d + 255) / 256, 256>>>(x, n * d);

    pos_pass<<<(n + 7) / 8, 256>>>(x, t, n, d);

    dim3 grid2(n / BT, n / BT);
    size_t smem_sz = 4 * TILE_ELN * sizeof(__nv_bfloat16);
    neg_pass_tc<<<grid2, 256, smem_sz>>>(t, n, d);

    finalize<<<1, 256>>>(out, n);
}